// round 16
// baseline (speedup 1.0000x reference)
#include <cuda_runtime.h>
#include <cuda_bf16.h>

#define S_LEN 2048
#define TQ 64
#define TK 64
#define LOG2E 1.4426950408889634f

// 6 bf16 planes, padded stride 72 (144 B rows: 16B-aligned, 4-bank shift/row)
#define PS 72
#define PLANE (64 * PS * 2)          // 9216 B
#define OFF_P0 0                     // Q-hi
#define OFF_P1 PLANE                 // Q-lo
#define OFF_P2 (2 * PLANE)           // K-hi
#define OFF_P3 (3 * PLANE)           // K-lo
#define OFF_P4 (4 * PLANE)           // V-hi
#define OFF_P5 (5 * PLANE)           // V-lo
#define OFF_L  (6 * PLANE)           // inv_l[64]
#define SMEM_SZ (OFF_L + 256)

__device__ __forceinline__ float ex2f(float x) {
    float r; asm("ex2.approx.ftz.f32 %0, %1;" : "=f"(r) : "f"(x)); return r;
}
__device__ __forceinline__ unsigned smem_u32(const void* p) {
    unsigned a;
    asm("{ .reg .u64 t; cvta.to.shared.u64 t, %1; cvt.u32.u64 %0, t; }" : "=r"(a) : "l"(p));
    return a;
}
__device__ __forceinline__ void mma16816(float d[4], const unsigned a[4],
                                         unsigned b0, unsigned b1) {
    asm volatile(
        "mma.sync.aligned.m16n8k16.row.col.f32.bf16.bf16.f32 "
        "{%0,%1,%2,%3}, {%4,%5,%6,%7}, {%8,%9}, {%0,%1,%2,%3};"
        : "+f"(d[0]), "+f"(d[1]), "+f"(d[2]), "+f"(d[3])
        : "r"(a[0]), "r"(a[1]), "r"(a[2]), "r"(a[3]), "r"(b0), "r"(b1));
}
#define LDSM4(r, a) asm volatile( \
    "ldmatrix.sync.aligned.m8n8.x4.shared.b16 {%0,%1,%2,%3}, [%4];" \
    : "=r"((r)[0]), "=r"((r)[1]), "=r"((r)[2]), "=r"((r)[3]) : "r"(a))
#define LDSM4T(r, a) asm volatile( \
    "ldmatrix.sync.aligned.m8n8.x4.trans.shared.b16 {%0,%1,%2,%3}, [%4];" \
    : "=r"((r)[0]), "=r"((r)[1]), "=r"((r)[2]), "=r"((r)[3]) : "r"(a))

// split (x,y) into hi/lo bf16x2 (low half = x)
__device__ __forceinline__ unsigned pack_split(float x, float y, unsigned& lo) {
    __nv_bfloat16 hx = __float2bfloat16(x), hy = __float2bfloat16(y);
    float rx = x - __bfloat162float(hx), ry = y - __bfloat162float(hy);
    __nv_bfloat16 lx = __float2bfloat16(rx), ly = __float2bfloat16(ry);
    lo = ((unsigned)__bfloat16_as_ushort(ly) << 16) | __bfloat16_as_ushort(lx);
    return ((unsigned)__bfloat16_as_ushort(hy) << 16) | __bfloat16_as_ushort(hx);
}

__global__ __launch_bounds__(128, 3)
void attn_fused(const float* __restrict__ Qg, const float* __restrict__ Kg,
                const float* __restrict__ Vg, const int* __restrict__ Mg,
                float* __restrict__ Out, float* __restrict__ Pg)
{
    extern __shared__ __align__(16) char sm[];
    const unsigned sb = smem_u32(sm);
    float* sL = (float*)(sm + OFF_L);
    const int tid = threadIdx.x, lane = tid & 31, wid = tid >> 5;
    const int g = lane >> 2, t = lane & 3;
    const int bh = blockIdx.x;
    const int q0 = blockIdx.y * TQ;
    const int wr = wid * 16;
    const int acol = 2 * t;

    // ldmatrix lane address components
    const int qrow = (lane & 7) + ((lane >> 3) & 1) * 8;   // A / trans-B row
    const int qcol = (lane >> 4) * 8;                       // A / trans-B col
    const int krow = (lane & 7) + (lane >> 4) * 8;          // non-trans B row
    const int kcol = ((lane >> 3) & 1) * 8;

    const float* qg = Qg + ((size_t)bh * S_LEN + q0) * 64;
    const float* kg = Kg + (size_t)bh * S_LEN * 64;
    const float* vg = Vg + (size_t)bh * S_LEN * 64;
    const int row0 = q0 + wr + g;
    const int* mp0 = Mg + (size_t)(bh >> 4) * S_LEN * S_LEN + (size_t)row0 * S_LEN;
    const int* mp8 = mp0 + 8 * S_LEN;
    float* ppB = Pg + ((size_t)bh * S_LEN + q0) * S_LEN;    // CTA p-slab base
    float* pp0 = Pg + ((size_t)bh * S_LEN + row0) * S_LEN;
    float* pp8 = pp0 + 8 * S_LEN;
    float* op0 = Out + ((size_t)bh * S_LEN + row0) * 64;
    float* op8 = op0 + 8 * 64;

    // ---- Q fill: scale by 1/8, split hi/lo, uint4 stores ----
    for (int i = tid; i < 64 * 8; i += 128) {
        int r = i >> 3, c = (i & 7) * 8;
        float4 a = *(const float4*)(qg + r * 64 + c);
        float4 b = *(const float4*)(qg + r * 64 + c + 4);
        a.x *= 0.125f; a.y *= 0.125f; a.z *= 0.125f; a.w *= 0.125f;
        b.x *= 0.125f; b.y *= 0.125f; b.z *= 0.125f; b.w *= 0.125f;
        uint4 H, L;
        H.x = pack_split(a.x, a.y, L.x); H.y = pack_split(a.z, a.w, L.y);
        H.z = pack_split(b.x, b.y, L.z); H.w = pack_split(b.z, b.w, L.w);
        *(uint4*)(sm + OFF_P0 + (r * PS + c) * 2) = H;
        *(uint4*)(sm + OFF_P1 + (r * PS + c) * 2) = L;
    }

    float lA = 0.f, lB = 0.f;
    float O[8][4];
    #pragma unroll
    for (int j = 0; j < 8; ++j)
        #pragma unroll
        for (int u = 0; u < 4; ++u) O[j][u] = 0.f;

    // ============ fused loop: S = QK^T, e, raw-e store, O += e V ============
    for (int kt = 0; kt < S_LEN; kt += TK) {
        __syncthreads();                       // protect prev K/V planes
        for (int i = tid; i < 64 * 8; i += 128) {   // K fill
            int r = i >> 3, c = (i & 7) * 8;
            float4 a = *(const float4*)(kg + (size_t)(kt + r) * 64 + c);
            float4 b = *(const float4*)(kg + (size_t)(kt + r) * 64 + c + 4);
            uint4 H, L;
            H.x = pack_split(a.x, a.y, L.x); H.y = pack_split(a.z, a.w, L.y);
            H.z = pack_split(b.x, b.y, L.z); H.w = pack_split(b.z, b.w, L.w);
            *(uint4*)(sm + OFF_P2 + (r * PS + c) * 2) = H;
            *(uint4*)(sm + OFF_P3 + (r * PS + c) * 2) = L;
        }
        for (int i = tid; i < 64 * 8; i += 128) {   // V fill (row-major)
            int r = i >> 3, c = (i & 7) * 8;
            float4 a = *(const float4*)(vg + (size_t)(kt + r) * 64 + c);
            float4 b = *(const float4*)(vg + (size_t)(kt + r) * 64 + c + 4);
            uint4 H, L;
            H.x = pack_split(a.x, a.y, L.x); H.y = pack_split(a.z, a.w, L.y);
            H.z = pack_split(b.x, b.y, L.z); H.w = pack_split(b.z, b.w, L.w);
            *(uint4*)(sm + OFF_P4 + (r * PS + c) * 2) = H;
            *(uint4*)(sm + OFF_P5 + (r * PS + c) * 2) = L;
        }
        __syncthreads();

        // ---- S = QK^T ----
        float S[8][4];
        #pragma unroll
        for (int j = 0; j < 8; ++j)
            #pragma unroll
            for (int u = 0; u < 4; ++u) S[j][u] = 0.f;

        #pragma unroll
        for (int kc = 0; kc < 4; ++kc) {
            unsigned ah[4], al[4];
            const unsigned qa = sb + OFF_P0 + ((wr + qrow) * PS + kc * 16 + qcol) * 2;
            LDSM4(ah, qa);
            LDSM4(al, qa + PLANE);
            #pragma unroll
            for (int jp = 0; jp < 4; ++jp) {
                unsigned kh[4], kl[4];
                const unsigned ka = sb + OFF_P2 +
                    ((jp * 16 + krow) * PS + kc * 16 + kcol) * 2;
                LDSM4(kh, ka);
                LDSM4(kl, ka + PLANE);
                mma16816(S[2*jp],   ah, kh[0], kh[1]);
                mma16816(S[2*jp],   al, kh[0], kh[1]);
                mma16816(S[2*jp],   ah, kl[0], kl[1]);
                mma16816(S[2*jp+1], ah, kh[2], kh[3]);
                mma16816(S[2*jp+1], al, kh[2], kh[3]);
                mma16816(S[2*jp+1], ah, kl[2], kl[3]);
            }
        }

        // ---- e = mask * exp(s); l accumulate; raw-e store (in-register reuse) ----
        #pragma unroll
        for (int j = 0; j < 8; ++j) {
            const int col = kt + j * 8 + acol;
            int2 m0 = *(const int2*)(mp0 + col);
            int2 m1 = *(const int2*)(mp8 + col);
            float e0 = m0.x ? ex2f(S[j][0] * LOG2E) : 0.f;
            float e1 = m0.y ? ex2f(S[j][1] * LOG2E) : 0.f;
            float e2 = m1.x ? ex2f(S[j][2] * LOG2E) : 0.f;
            float e3 = m1.y ? ex2f(S[j][3] * LOG2E) : 0.f;
            lA += e0 + e1;
            lB += e2 + e3;
            *(float2*)(pp0 + col) = make_float2(e0, e1);   // raw e (scratch)
            *(float2*)(pp8 + col) = make_float2(e2, e3);
            S[j][0] = e0; S[j][1] = e1; S[j][2] = e2; S[j][3] = e3;
        }

        // ---- O += e V  (e packed straight from registers) ----
        #pragma unroll
        for (int kc = 0; kc < 4; ++kc) {
            unsigned ah[4], al[4];
            ah[0] = pack_split(S[2*kc][0],   S[2*kc][1],   al[0]);
            ah[1] = pack_split(S[2*kc][2],   S[2*kc][3],   al[1]);
            ah[2] = pack_split(S[2*kc+1][0], S[2*kc+1][1], al[2]);
            ah[3] = pack_split(S[2*kc+1][2], S[2*kc+1][3], al[3]);
            #pragma unroll
            for (int jdp = 0; jdp < 4; ++jdp) {
                unsigned vh[4], vl[4];
                const unsigned va = sb + OFF_P4 +
                    ((kc * 16 + qrow) * PS + jdp * 16 + qcol) * 2;
                LDSM4T(vh, va);
                LDSM4T(vl, va + PLANE);
                mma16816(O[2*jdp],   ah, vh[0], vh[1]);
                mma16816(O[2*jdp],   al, vh[0], vh[1]);
                mma16816(O[2*jdp],   ah, vl[0], vl[1]);
                mma16816(O[2*jdp+1], ah, vh[2], vh[3]);
                mma16816(O[2*jdp+1], al, vh[2], vh[3]);
                mma16816(O[2*jdp+1], ah, vl[2], vl[3]);
            }
        }
    }

    // ---- row sums -> inv; out = O * inv ----
    lA += __shfl_xor_sync(0xffffffffu, lA, 1);
    lA += __shfl_xor_sync(0xffffffffu, lA, 2);
    lB += __shfl_xor_sync(0xffffffffu, lB, 1);
    lB += __shfl_xor_sync(0xffffffffu, lB, 2);
    const float invA = 1.f / lA, invB = 1.f / lB;
    if (t == 0) {
        sL[wr + g] = invA;
        sL[wr + g + 8] = invB;
    }
    #pragma unroll
    for (int jd = 0; jd < 8; ++jd) {
        *(float2*)(op0 + jd * 8 + acol) =
            make_float2(O[jd][0] * invA, O[jd][1] * invA);
        *(float2*)(op8 + jd * 8 + acol) =
            make_float2(O[jd][2] * invB, O[jd][3] * invB);
    }
    __syncthreads();   // sL visible + all raw-e global writes visible in CTA

    // ---- streaming rescale of own p-slab: p = e * inv_l[row] ----
    for (int i = tid; i < 64 * (S_LEN / 4); i += 128) {
        const int r = i >> 9;                 // 512 float4 per row
        const int c = (i & 511) * 4;
        float* gp = ppB + (size_t)r * S_LEN + c;
        float4 e = __ldcs((const float4*)gp);
        const float il = sL[r];
        e.x *= il; e.y *= il; e.z *= il; e.w *= il;
        __stcs((float4*)gp, e);
    }
}

extern "C" void kernel_launch(void* const* d_in, const int* in_sizes, int n_in,
                              void* d_out, int out_size)
{
    const float* q = (const float*)d_in[0];
    const float* k = (const float*)d_in[1];
    const float* v = (const float*)d_in[2];
    const int*   m = (const int*)d_in[3];
    float* out = (float*)d_out;
    float* p   = out + (size_t)2 * 16 * 2048 * 64;

    cudaFuncSetAttribute(attn_fused, cudaFuncAttributeMaxDynamicSharedMemorySize, SMEM_SZ);
    dim3 grid(2 * 16, S_LEN / TQ);   // bh-major: heads sharing mask run together
    attn_fused<<<grid, 128, SMEM_SZ>>>(q, k, v, m, out, p);
}

// round 17
// speedup vs baseline: 1.6084x; 1.6084x over previous
#include <cuda_runtime.h>
#include <cuda_bf16.h>

#define S_LEN 2048
#define TQ 64
#define TK 64
#define LOG2E 1.4426950408889634f

// 4 bf16 planes, padded stride 72 (144 B rows: 16B-aligned, 4-bank shift/row)
#define PS 72
#define PLANE (64 * PS * 2)          // 9216 B
#define OFF_P0 0                     // Q-hi
#define OFF_P1 PLANE                 // Q-lo
#define OFF_P2 (2 * PLANE)           // K-hi | V-hi
#define OFF_P3 (3 * PLANE)           // K-lo | V-lo
#define SMEM_SZ (4 * PLANE)          // 36864 B

__device__ __forceinline__ float ex2f(float x) {
    float r; asm("ex2.approx.ftz.f32 %0, %1;" : "=f"(r) : "f"(x)); return r;
}
__device__ __forceinline__ unsigned smem_u32(const void* p) {
    unsigned a;
    asm("{ .reg .u64 t; cvta.to.shared.u64 t, %1; cvt.u32.u64 %0, t; }" : "=r"(a) : "l"(p));
    return a;
}
__device__ __forceinline__ void mma16816(float d[4], const unsigned a[4],
                                         unsigned b0, unsigned b1) {
    asm volatile(
        "mma.sync.aligned.m16n8k16.row.col.f32.bf16.bf16.f32 "
        "{%0,%1,%2,%3}, {%4,%5,%6,%7}, {%8,%9}, {%0,%1,%2,%3};"
        : "+f"(d[0]), "+f"(d[1]), "+f"(d[2]), "+f"(d[3])
        : "r"(a[0]), "r"(a[1]), "r"(a[2]), "r"(a[3]), "r"(b0), "r"(b1));
}
#define LDSM4(r, a) asm volatile( \
    "ldmatrix.sync.aligned.m8n8.x4.shared.b16 {%0,%1,%2,%3}, [%4];" \
    : "=r"((r)[0]), "=r"((r)[1]), "=r"((r)[2]), "=r"((r)[3]) : "r"(a))
#define LDSM4T(r, a) asm volatile( \
    "ldmatrix.sync.aligned.m8n8.x4.trans.shared.b16 {%0,%1,%2,%3}, [%4];" \
    : "=r"((r)[0]), "=r"((r)[1]), "=r"((r)[2]), "=r"((r)[3]) : "r"(a))

// split (x,y) into hi/lo bf16x2 (low half = x)
__device__ __forceinline__ unsigned pack_split(float x, float y, unsigned& lo) {
    __nv_bfloat16 hx = __float2bfloat16(x), hy = __float2bfloat16(y);
    float rx = x - __bfloat162float(hx), ry = y - __bfloat162float(hy);
    __nv_bfloat16 lx = __float2bfloat16(rx), ly = __float2bfloat16(ry);
    lo = ((unsigned)__bfloat16_as_ushort(ly) << 16) | __bfloat16_as_ushort(lx);
    return ((unsigned)__bfloat16_as_ushort(hy) << 16) | __bfloat16_as_ushort(hx);
}

__global__ __launch_bounds__(128, 5)
void attn_mma(const float* __restrict__ Qg, const float* __restrict__ Kg,
              const float* __restrict__ Vg, const int* __restrict__ Mg,
              float* __restrict__ Out, float* __restrict__ Pg)
{
    extern __shared__ __align__(16) char sm[];
    const unsigned sb = smem_u32(sm);
    const int tid = threadIdx.x, lane = tid & 31, wid = tid >> 5;
    const int g = lane >> 2, t = lane & 3;
    const int bh = blockIdx.x;
    const int q0 = blockIdx.y * TQ;
    const int wr = wid * 16;
    const int acol = 2 * t;

    // ldmatrix lane address components
    const int qrow = (lane & 7) + ((lane >> 3) & 1) * 8;   // A / trans-B row
    const int qcol = (lane >> 4) * 8;                       // A / trans-B col
    const int krow = (lane & 7) + (lane >> 4) * 8;          // non-trans B row
    const int kcol = ((lane >> 3) & 1) * 8;

    const float* qg = Qg + ((size_t)bh * S_LEN + q0) * 64;
    const float* kg = Kg + (size_t)bh * S_LEN * 64;
    const float* vg = Vg + (size_t)bh * S_LEN * 64;
    const int row0 = q0 + wr + g;
    const int* mp0 = Mg + (size_t)(bh >> 4) * S_LEN * S_LEN + (size_t)row0 * S_LEN;
    const int* mp8 = mp0 + 8 * S_LEN;
    float* pp0 = Pg + ((size_t)bh * S_LEN + row0) * S_LEN;
    float* pp8 = pp0 + 8 * S_LEN;
    float* op0 = Out + ((size_t)bh * S_LEN + row0) * 64;
    float* op8 = op0 + 8 * 64;

    // ---- Q fill: scale by 1/8, split hi/lo, uint4 stores ----
    #pragma unroll 4
    for (int i = tid; i < 64 * 8; i += 128) {
        int r = i >> 3, c = (i & 7) * 8;
        float4 a = *(const float4*)(qg + r * 64 + c);
        float4 b = *(const float4*)(qg + r * 64 + c + 4);
        a.x *= 0.125f; a.y *= 0.125f; a.z *= 0.125f; a.w *= 0.125f;
        b.x *= 0.125f; b.y *= 0.125f; b.z *= 0.125f; b.w *= 0.125f;
        uint4 H, L;
        H.x = pack_split(a.x, a.y, L.x); H.y = pack_split(a.z, a.w, L.y);
        H.z = pack_split(b.x, b.y, L.z); H.w = pack_split(b.z, b.w, L.w);
        *(uint4*)(sm + OFF_P0 + (r * PS + c) * 2) = H;
        *(uint4*)(sm + OFF_P1 + (r * PS + c) * 2) = L;
    }

    // ================= Pass A: S = QK^T, e = mask*exp(s), row sums =================
    float lA = 0.f, lB = 0.f;
    for (int kt = 0; kt < S_LEN; kt += TK) {
        __syncthreads();
        #pragma unroll 4
        for (int i = tid; i < 64 * 8; i += 128) {   // K fill
            int r = i >> 3, c = (i & 7) * 8;
            float4 a = *(const float4*)(kg + (size_t)(kt + r) * 64 + c);
            float4 b = *(const float4*)(kg + (size_t)(kt + r) * 64 + c + 4);
            uint4 H, L;
            H.x = pack_split(a.x, a.y, L.x); H.y = pack_split(a.z, a.w, L.y);
            H.z = pack_split(b.x, b.y, L.z); H.w = pack_split(b.z, b.w, L.w);
            *(uint4*)(sm + OFF_P2 + (r * PS + c) * 2) = H;
            *(uint4*)(sm + OFF_P3 + (r * PS + c) * 2) = L;
        }
        __syncthreads();

        float S[8][4];
        #pragma unroll
        for (int j = 0; j < 8; ++j)
            #pragma unroll
            for (int u = 0; u < 4; ++u) S[j][u] = 0.f;

        #pragma unroll
        for (int kc = 0; kc < 4; ++kc) {
            unsigned ah[4], al[4];
            const unsigned qa = sb + OFF_P0 + ((wr + qrow) * PS + kc * 16 + qcol) * 2;
            LDSM4(ah, qa);
            LDSM4(al, qa + PLANE);
            #pragma unroll
            for (int jp = 0; jp < 4; ++jp) {
                unsigned kh[4], kl[4];
                const unsigned ka = sb + OFF_P2 +
                    ((jp * 16 + krow) * PS + kc * 16 + kcol) * 2;
                LDSM4(kh, ka);
                LDSM4(kl, ka + PLANE);
                mma16816(S[2*jp],   ah, kh[0], kh[1]);
                mma16816(S[2*jp],   al, kh[0], kh[1]);
                mma16816(S[2*jp],   ah, kl[0], kl[1]);
                mma16816(S[2*jp+1], ah, kh[2], kh[3]);
                mma16816(S[2*jp+1], al, kh[2], kh[3]);
                mma16816(S[2*jp+1], ah, kl[2], kl[3]);
            }
        }

        #pragma unroll
        for (int j = 0; j < 8; ++j) {
            const int col = kt + j * 8 + acol;
            int2 m0 = *(const int2*)(mp0 + col);
            int2 m1 = *(const int2*)(mp8 + col);
            float e0 = m0.x ? ex2f(S[j][0] * LOG2E) : 0.f;
            float e1 = m0.y ? ex2f(S[j][1] * LOG2E) : 0.f;
            float e2 = m1.x ? ex2f(S[j][2] * LOG2E) : 0.f;
            float e3 = m1.y ? ex2f(S[j][3] * LOG2E) : 0.f;
            lA += e0 + e1;
            lB += e2 + e3;
            *(float2*)(pp0 + col) = make_float2(e0, e1);   // raw e (scratch)
            *(float2*)(pp8 + col) = make_float2(e2, e3);
        }
    }
    lA += __shfl_xor_sync(0xffffffffu, lA, 1);
    lA += __shfl_xor_sync(0xffffffffu, lA, 2);
    lB += __shfl_xor_sync(0xffffffffu, lB, 1);
    lB += __shfl_xor_sync(0xffffffffu, lB, 2);
    const float invA = 1.f / lA, invB = 1.f / lB;

    // ====== Pass B: per-thread e->p in fragment layout (no barrier dep),
    //        O += p V with row-major V + ldmatrix.trans ======
    float O[8][4];
    #pragma unroll
    for (int j = 0; j < 8; ++j)
        #pragma unroll
        for (int u = 0; u < 4; ++u) O[j][u] = 0.f;

    for (int kt = 0; kt < S_LEN; kt += TK) {
        __syncthreads();
        // V fill, row-major [tok][d], uint4 stores
        #pragma unroll 4
        for (int i = tid; i < 64 * 8; i += 128) {
            int r = i >> 3, c = (i & 7) * 8;
            float4 a = *(const float4*)(vg + (size_t)(kt + r) * 64 + c);
            float4 b = *(const float4*)(vg + (size_t)(kt + r) * 64 + c + 4);
            uint4 H, L;
            H.x = pack_split(a.x, a.y, L.x); H.y = pack_split(a.z, a.w, L.y);
            H.z = pack_split(b.x, b.y, L.z); H.w = pack_split(b.z, b.w, L.w);
            *(uint4*)(sm + OFF_P2 + (r * PS + c) * 2) = H;
            *(uint4*)(sm + OFF_P3 + (r * PS + c) * 2) = L;
        }
        __syncthreads();

        #pragma unroll
        for (int kc = 0; kc < 4; ++kc) {
            const int colA = kt + kc * 16 + acol;    // tokens for a0/a1
            const int colB = colA + 8;               // tokens for a2/a3
            float2 ea0 = *(const float2*)(pp0 + colA);
            float2 ea1 = *(const float2*)(pp8 + colA);
            float2 eb0 = *(const float2*)(pp0 + colB);
            float2 eb1 = *(const float2*)(pp8 + colB);
            float p00 = ea0.x * invA, p01 = ea0.y * invA;
            float p08 = ea1.x * invB, p09 = ea1.y * invB;
            float p10 = eb0.x * invA, p11 = eb0.y * invA;
            float p18 = eb1.x * invB, p19 = eb1.y * invB;
            *(float2*)(pp0 + colA) = make_float2(p00, p01);   // final p
            *(float2*)(pp8 + colA) = make_float2(p08, p09);
            *(float2*)(pp0 + colB) = make_float2(p10, p11);
            *(float2*)(pp8 + colB) = make_float2(p18, p19);

            unsigned ah[4], al[4];
            ah[0] = pack_split(p00, p01, al[0]);
            ah[1] = pack_split(p08, p09, al[1]);
            ah[2] = pack_split(p10, p11, al[2]);
            ah[3] = pack_split(p18, p19, al[3]);

            #pragma unroll
            for (int jdp = 0; jdp < 4; ++jdp) {
                unsigned vh[4], vl[4];
                const unsigned va = sb + OFF_P2 +
                    ((kc * 16 + qrow) * PS + jdp * 16 + qcol) * 2;
                LDSM4T(vh, va);
                LDSM4T(vl, va + PLANE);
                mma16816(O[2*jdp],   ah, vh[0], vh[1]);
                mma16816(O[2*jdp],   al, vh[0], vh[1]);
                mma16816(O[2*jdp],   ah, vl[0], vl[1]);
                mma16816(O[2*jdp+1], ah, vh[2], vh[3]);
                mma16816(O[2*jdp+1], al, vh[2], vh[3]);
                mma16816(O[2*jdp+1], ah, vl[2], vl[3]);
            }
        }
    }

    // ---- out (already normalized) ----
    #pragma unroll
    for (int jd = 0; jd < 8; ++jd) {
        *(float2*)(op0 + jd * 8 + acol) = make_float2(O[jd][0], O[jd][1]);
        *(float2*)(op8 + jd * 8 + acol) = make_float2(O[jd][2], O[jd][3]);
    }
}

extern "C" void kernel_launch(void* const* d_in, const int* in_sizes, int n_in,
                              void* d_out, int out_size)
{
    const float* q = (const float*)d_in[0];
    const float* k = (const float*)d_in[1];
    const float* v = (const float*)d_in[2];
    const int*   m = (const int*)d_in[3];
    float* out = (float*)d_out;
    float* p   = out + (size_t)2 * 16 * 2048 * 64;

    cudaFuncSetAttribute(attn_mma, cudaFuncAttributeMaxDynamicSharedMemorySize, SMEM_SZ);
    dim3 grid(2 * 16, S_LEN / TQ);   // bh-major: heads sharing mask run together
    attn_mma<<<grid, 128, SMEM_SZ>>>(q, k, v, m, out, p);
}